// round 1
// baseline (speedup 1.0000x reference)
#include <cuda_runtime.h>
#include <math.h>

#define HH 192
#define WWID 192
#define HW (192*192)
#define NB 4
#define ND 8

// ---------------- scratch (static device globals; no runtime alloc) -------------
__device__ float g_hs[NB * 8 * HW];      // h state
__device__ float g_r [NB * 40 * HW];     // [c_state(8) | q(32)]  (c carry = ch 0..7)
__device__ float g_gate[NB * 56 * HW];   // raw gate conv outputs (f,i,g,q)
__device__ float g_y0[NB * 40 * HW];     // conv0 raw output
__device__ float g_y1[NB * 40 * HW];     // conv1 raw output
__device__ float g_stats[80];            // [scale(40) | shift(40)]
__device__ float g_Wg[56 * 40 * 9];      // packed gate weights
__device__ float g_bg[56];               // packed gate biases

// ---------------- init ------------------------------------------------------
__global__ void zero_state() {
    int stride = gridDim.x * blockDim.x;
    int i0 = blockIdx.x * blockDim.x + threadIdx.x;
    for (int i = i0; i < NB * 8 * HW; i += stride) g_hs[i] = 0.f;
    for (int i = i0; i < NB * 40 * HW; i += stride) g_r[i] = 0.f;
}

__global__ void pack_gates(const float* __restrict__ Wf, const float* __restrict__ bf,
                           const float* __restrict__ Wi, const float* __restrict__ bi,
                           const float* __restrict__ Wc, const float* __restrict__ bc,
                           const float* __restrict__ Wq, const float* __restrict__ bq) {
    const int WSZ = 40 * 9;
    int i = blockIdx.x * blockDim.x + threadIdx.x;
    if (i < 56 * WSZ) {
        int cout = i / WSZ, rest = i - cout * WSZ;
        float v;
        if (cout < 8)       v = Wf[cout * WSZ + rest];
        else if (cout < 16) v = Wi[(cout - 8) * WSZ + rest];
        else if (cout < 24) v = Wc[(cout - 16) * WSZ + rest];
        else                v = Wq[(cout - 24) * WSZ + rest];
        g_Wg[i] = v;
    }
    if (i < 56) {
        float v;
        if (i < 8)       v = bf[i];
        else if (i < 16) v = bi[i - 8];
        else if (i < 24) v = bc[i - 16];
        else             v = bq[i - 24];
        g_bg[i] = v;
    }
}

// ---------------- generic direct conv ---------------------------------------
// Output tile: 32 x TILE_H per block. Threads (32, TY, CG).
// Each thread: P = TILE_H/TY pixel rows, CPG = COUT/CG output channels.
// Input channel c < CA comes from inA, else from inB (channel c-CA)  -> fused concat.
// PREOP: v = relu(scale[cin]*v + shift[cin]) folded into the tile load (BN+ReLU).
template<int CIN, int CA, int COUT, int K, int TILE_H, int TY, int CG, bool PREOP, bool HASBIAS>
__global__ void __launch_bounds__(32 * TY * CG)
conv_generic(const float* __restrict__ inA, int strideA,
             const float* __restrict__ inB, int strideB,
             const float* __restrict__ wgt,   // [COUT, CIN, K, K]
             const float* __restrict__ bias,  // [COUT] (if HASBIAS)
             const float* __restrict__ stats, // [2*CIN] (if PREOP)
             float* __restrict__ out, int strideOut, int chanStrideOut)
{
    constexpr int P = TILE_H / TY;
    constexpr int CPG = COUT / CG;
    constexpr int PAD = K / 2;
    constexpr int IN_TW = 32 + K - 1;
    constexpr int IN_TH = TILE_H + K - 1;
    constexpr int NT = 32 * TY * CG;

    __shared__ float s_in[IN_TH * IN_TW];
    __shared__ float s_w[COUT * K * K];

    const int tx = threadIdx.x, ty = threadIdx.y, cg = threadIdx.z;
    const int tid = (cg * TY + ty) * 32 + tx;
    const int bx = blockIdx.x, by = blockIdx.y, n = blockIdx.z;
    const int gx = bx * 32 + tx;
    const int gy0 = by * TILE_H;

    float acc[CPG][P];
#pragma unroll
    for (int c = 0; c < CPG; c++)
#pragma unroll
        for (int p = 0; p < P; p++) acc[c][p] = 0.f;

    for (int cin = 0; cin < CIN; cin++) {
        const float* src = (cin < CA)
            ? (inA + (size_t)n * strideA + (size_t)cin * HW)
            : (inB + (size_t)n * strideB + (size_t)(cin - CA) * HW);
        float sc = 1.f, sh = 0.f;
        if constexpr (PREOP) { sc = stats[cin]; sh = stats[CIN + cin]; }

        // stage input tile (+halo) for this input channel
        for (int idx = tid; idx < IN_TH * IN_TW; idx += NT) {
            int iy = idx / IN_TW, ix = idx - iy * IN_TW;
            int yy = gy0 + iy - PAD;
            int xx = bx * 32 + ix - PAD;
            float v = 0.f;
            if (yy >= 0 && yy < HH && xx >= 0 && xx < WWID) {
                v = src[yy * WWID + xx];
                if constexpr (PREOP) v = fmaxf(fmaf(sc, v, sh), 0.f);
            }
            s_in[idx] = v;
        }
        // stage this cin's weight slice for all couts
        for (int idx = tid; idx < COUT * K * K; idx += NT) {
            int cout = idx / (K * K);
            int k = idx - cout * (K * K);
            s_w[idx] = wgt[((size_t)cout * CIN + cin) * (K * K) + k];
        }
        __syncthreads();

#pragma unroll
        for (int ky = 0; ky < K; ky++) {
            float iv[P][K];
#pragma unroll
            for (int p = 0; p < P; p++) {
                int row = ty + p * TY + ky;
#pragma unroll
                for (int kx = 0; kx < K; kx++)
                    iv[p][kx] = s_in[row * IN_TW + tx + kx];
            }
#pragma unroll
            for (int c = 0; c < CPG; c++) {
                const float* wrow = &s_w[(cg * CPG + c) * (K * K) + ky * K];
#pragma unroll
                for (int kx = 0; kx < K; kx++) {
                    float wv = wrow[kx];
#pragma unroll
                    for (int p = 0; p < P; p++)
                        acc[c][p] = fmaf(iv[p][kx], wv, acc[c][p]);
                }
            }
        }
        __syncthreads();
    }

#pragma unroll
    for (int c = 0; c < CPG; c++) {
        int cout = cg * CPG + c;
        float bv = 0.f;
        if constexpr (HASBIAS) bv = bias[cout];
#pragma unroll
        for (int p = 0; p < P; p++) {
            int gy = gy0 + ty + p * TY;
            out[(size_t)n * strideOut + (size_t)cout * chanStrideOut + gy * WWID + gx]
                = acc[c][p] + bv;
        }
    }
}

// ---------------- LSTM pointwise cell update --------------------------------
__global__ void cell_pointwise(const float* __restrict__ gate, float* __restrict__ r) {
    int i = blockIdx.x * blockDim.x + threadIdx.x;
    if (i >= NB * HW) return;
    int n = i / HW, p = i - n * HW;
    const float* gb = gate + (size_t)n * 56 * HW + p;
    float* rb = r + (size_t)n * 40 * HW + p;
#pragma unroll
    for (int c = 0; c < 8; c++) {
        float f  = 1.f / (1.f + expf(-gb[(size_t)c * HW]));
        float ii = 1.f / (1.f + expf(-gb[(size_t)(8 + c) * HW]));
        float gg = tanhf(gb[(size_t)(16 + c) * HW]);
        float cso = rb[(size_t)c * HW];
        rb[(size_t)c * HW] = f * cso + ii * gg;
    }
#pragma unroll
    for (int j = 0; j < 32; j++) {
        rb[(size_t)(8 + j) * HW] = 1.f / (1.f + expf(-gb[(size_t)(24 + j) * HW]));
    }
}

// ---------------- BN batch statistics -> (scale, shift) ---------------------
__global__ void bn_stats(const float* __restrict__ y, const float* __restrict__ gamma,
                         const float* __restrict__ beta, float* __restrict__ stats) {
    int c = blockIdx.x;
    float s = 0.f, s2 = 0.f;
    for (int n = 0; n < NB; n++) {
        const float* yp = y + ((size_t)n * 40 + c) * HW;
        for (int p = threadIdx.x; p < HW; p += blockDim.x) {
            float v = yp[p];
            s += v;
            s2 = fmaf(v, v, s2);
        }
    }
    __shared__ float rs[256], rs2[256];
    rs[threadIdx.x] = s; rs2[threadIdx.x] = s2;
    __syncthreads();
    for (int off = 128; off > 0; off >>= 1) {
        if (threadIdx.x < off) {
            rs[threadIdx.x] += rs[threadIdx.x + off];
            rs2[threadIdx.x] += rs2[threadIdx.x + off];
        }
        __syncthreads();
    }
    if (threadIdx.x == 0) {
        const float N = (float)(NB * HW);
        float mean = rs[0] / N;
        float var = rs2[0] / N - mean * mean;
        float sc = gamma[c] * rsqrtf(var + 1e-5f);
        stats[c] = sc;
        stats[40 + c] = beta[c] - mean * sc;
    }
}

// ---------------- driver -----------------------------------------------------
extern "C" void kernel_launch(void* const* d_in, const int* in_sizes, int n_in,
                              void* d_out, int out_size) {
    const float* x1  = (const float*)d_in[0];
    const float* x2  = (const float*)d_in[1];
    const float* Wf  = (const float*)d_in[2];
    const float* bf  = (const float*)d_in[3];
    const float* Wi  = (const float*)d_in[4];
    const float* bi  = (const float*)d_in[5];
    const float* Wc  = (const float*)d_in[6];
    const float* bc  = (const float*)d_in[7];
    const float* Wq  = (const float*)d_in[8];
    const float* bq  = (const float*)d_in[9];
    const float* W0  = (const float*)d_in[10];
    const float* g0  = (const float*)d_in[11];
    const float* be0 = (const float*)d_in[12];
    const float* W1  = (const float*)d_in[13];
    const float* g1  = (const float*)d_in[14];
    const float* be1 = (const float*)d_in[15];
    const float* W2  = (const float*)d_in[16];
    const float* b2w = (const float*)d_in[17];
    const float* Wh  = (const float*)d_in[18];
    const float* bh  = (const float*)d_in[19];
    float* out = (float*)d_out;

    float *hs, *r, *gate, *y0, *y1, *stats, *Wg, *bg;
    cudaGetSymbolAddress((void**)&hs,    g_hs);
    cudaGetSymbolAddress((void**)&r,     g_r);
    cudaGetSymbolAddress((void**)&gate,  g_gate);
    cudaGetSymbolAddress((void**)&y0,    g_y0);
    cudaGetSymbolAddress((void**)&y1,    g_y1);
    cudaGetSymbolAddress((void**)&stats, g_stats);
    cudaGetSymbolAddress((void**)&Wg,    g_Wg);
    cudaGetSymbolAddress((void**)&bg,    g_bg);

    zero_state<<<1024, 256>>>();
    pack_gates<<<(56 * 360 + 255) / 256, 256>>>(Wf, bf, Wi, bi, Wc, bc, Wq, bq);

    for (int t = 0; t < ND; t++) {
        for (int s = 0; s < 2; s++) {
            const float* x = (s == 0 ? x1 : x2) + (size_t)t * 32 * HW;

            // 1) gate conv 3x3: ic = [x(32) | hs(8)] -> 56 raw channels
            conv_generic<40, 32, 56, 3, 8, 2, 8, false, true>
                <<<dim3(6, 24, NB), dim3(32, 2, 8)>>>(
                    x, ND * 32 * HW, hs, 8 * HW, Wg, bg, nullptr,
                    gate, 56 * HW, HW);

            // 2) LSTM pointwise: c' = sig(f)*c + sig(i)*tanh(g); r = [c' | sig(q)]
            cell_pointwise<<<(NB * HW + 255) / 256, 256>>>(gate, r);

            // 3) conv0 5x5 40->40 (raw, BN applied by consumer)
            conv_generic<40, 40, 40, 5, 16, 4, 4, false, false>
                <<<dim3(6, 12, NB), dim3(32, 4, 4)>>>(
                    r, 40 * HW, nullptr, 0, W0, nullptr, nullptr,
                    y0, 40 * HW, HW);

            // 4) BN stats for y0
            bn_stats<<<40, 256>>>(y0, g0, be0, stats);

            // 5) conv1 5x5 40->40, BN+ReLU of y0 fused into input load
            conv_generic<40, 40, 40, 5, 16, 4, 4, true, false>
                <<<dim3(6, 12, NB), dim3(32, 4, 4)>>>(
                    y0, 40 * HW, nullptr, 0, W1, nullptr, stats,
                    y1, 40 * HW, HW);

            // 6) BN stats for y1
            bn_stats<<<40, 256>>>(y1, g1, be1, stats);

            // 7) new h-state: conv 3x3 40->8 (BN+ReLU fused on input)
            conv_generic<40, 40, 8, 3, 16, 8, 2, true, true>
                <<<dim3(6, 12, NB), dim3(32, 8, 2)>>>(
                    y1, 40 * HW, nullptr, 0, Wh, bh, stats,
                    hs, 8 * HW, HW);

            // 8) output head: conv 5x5 40->3 into d_out[(b,3,d,H,W)] slice
            conv_generic<40, 40, 3, 5, 16, 8, 1, true, true>
                <<<dim3(6, 12, NB), dim3(32, 8, 1)>>>(
                    y1, 40 * HW, nullptr, 0, W2, b2w, stats,
                    out + (size_t)s * (NB * 3 * ND * HW) + (size_t)t * HW,
                    3 * ND * HW, ND * HW);
        }
    }
}